// round 16
// baseline (speedup 1.0000x reference)
#include <cuda_runtime.h>
#include <cuda_bf16.h>
#include <cstdint>

// Problem constants
#define BB   128
#define TT   500
#define NIN  784
#define HH   1024
#define NS   102
#define DECAY 0.8807970779778823f      // sigmoid(2.0)
#define KP   832                       // NIN padded (multiple of 32)
#define KC   32
#define NCH  (KP / KC)
#define TSTRIDE 80                     // phase-1 smem row stride
#define STG_BYTES (6 * 128 * TSTRIDE)  // one pipeline stage: 61,440 B

// Persistent recurrent decomposition
#define NBLK 128
#define NTHR 256
#define NJT  4
#define JTS  256                       // j per tile
#define HTS  32                        // h per tile
#define ASTR 528                       // smem row stride bytes (512 data + 16 pad)

// Scratch
__device__ float g_C[(size_t)BB * TT * HH];              // X @ fc1  (262 MB)
__device__ float g_part[NJT][BB][HH];                    // j-partials (2 MB)
__device__ __nv_bfloat16 g_spkb[2][BB * HH];             // spike state, bf16, dbl-buf
__device__ unsigned g_barA[NBLK];                        // barrier-site A flags
__device__ unsigned g_barB[NBLK];                        // barrier-site B flags
__device__ __nv_bfloat16 g_Xs[3][(size_t)BB * TT * KP];  // X splits (320 MB)
__device__ __nv_bfloat16 g_Wt[3][(size_t)HH * KP];       // fc1^T splits (5 MB)
__device__ __nv_bfloat16 g_Rt[3][(size_t)HH * HH];       // R^T splits (6 MB)

__device__ __forceinline__ uint32_t smem_u32(const void* p) {
    uint32_t a;
    asm("{ .reg .u64 t; cvta.to.shared.u64 t, %1; cvt.u32.u64 %0, t; }" : "=r"(a) : "l"(p));
    return a;
}

#define CP_ASYNC_CG(dst, src) \
    asm volatile("cp.async.cg.shared.global [%0], [%1], 16;" :: "r"(dst), "l"(src) : "memory")
#define CP_ASYNC_COMMIT() asm volatile("cp.async.commit_group;" ::: "memory")
#define CP_ASYNC_WAIT(n)  asm volatile("cp.async.wait_group %0;" :: "n"(n) : "memory")

__device__ __forceinline__ unsigned ld_acq(const unsigned* p) {
    unsigned v;
    asm volatile("ld.acquire.gpu.global.u32 %0, [%1];" : "=r"(v) : "l"(p) : "memory");
    return v;
}
__device__ __forceinline__ void st_rel(unsigned* p, unsigned v) {
    asm volatile("st.release.gpu.global.u32 [%0], %1;" :: "l"(p), "r"(v) : "memory");
}

// Decentralized grid barrier: each block publishes a monotone counter to its
// own slot; threads 0..NBLK-1 each poll one slot. One L2 visibility hop after
// the last arrival; no atomics, no sleep quantization.
__device__ __forceinline__ void grid_sync_arr(unsigned* arr, unsigned target) {
    __threadfence();
    __syncthreads();
    if (threadIdx.x == 0) st_rel(&arr[blockIdx.x], target);
    if (threadIdx.x < NBLK)
        while (ld_acq(&arr[threadIdx.x]) < target) { }
    __syncthreads();
}

// ---------------------------------------------------------------------------
__global__ void init_kernel(float* __restrict__ out, int out_size) {
    int i = blockIdx.x * blockDim.x + threadIdx.x;
    if (i < BB * HH) {
        g_spkb[0][i] = __float2bfloat16_rn(0.f);
        g_spkb[1][i] = __float2bfloat16_rn(0.f);
    }
    if (i < NBLK) { g_barA[i] = 0u; g_barB[i] = 0u; }
    int tail = out_size - BB * TT * NS;
    if (tail > 0 && i < tail) out[BB * TT * NS + i] = 500.0f;
}

// ---------------------------------------------------------------------------
// Exact 3-term bf16 splits.
// ---------------------------------------------------------------------------
__global__ void split_x_kernel(const float* __restrict__ X) {
    int i = blockIdx.x * blockDim.x + threadIdx.x;
    if (i >= BB * TT * (KP / 2)) return;
    int m = i / (KP / 2);
    int k = (i % (KP / 2)) * 2;
    float v0 = 0.f, v1 = 0.f;
    if (k < NIN) { v0 = X[(size_t)m * NIN + k]; v1 = X[(size_t)m * NIN + k + 1]; }
    __nv_bfloat16 a1 = __float2bfloat16_rn(v0);
    float r = v0 - __bfloat162float(a1);
    __nv_bfloat16 a2 = __float2bfloat16_rn(r);
    __nv_bfloat16 a3 = __float2bfloat16_rn(r - __bfloat162float(a2));
    __nv_bfloat16 b1 = __float2bfloat16_rn(v1);
    float r2 = v1 - __bfloat162float(b1);
    __nv_bfloat16 b2 = __float2bfloat16_rn(r2);
    __nv_bfloat16 b3 = __float2bfloat16_rn(r2 - __bfloat162float(b2));
    size_t o = (size_t)m * KP + k;
    *(__nv_bfloat162*)&g_Xs[0][o] = __nv_bfloat162(a1, b1);
    *(__nv_bfloat162*)&g_Xs[1][o] = __nv_bfloat162(a2, b2);
    *(__nv_bfloat162*)&g_Xs[2][o] = __nv_bfloat162(a3, b3);
}

__global__ void split_w_kernel(const float* __restrict__ W) {
    int i = blockIdx.x * blockDim.x + threadIdx.x;
    if (i >= HH * (KP / 2)) return;
    int n = i / (KP / 2);
    int k = (i % (KP / 2)) * 2;
    float v0 = (k < NIN)     ? W[(size_t)k * HH + n]       : 0.f;
    float v1 = (k + 1 < NIN) ? W[(size_t)(k + 1) * HH + n] : 0.f;
    __nv_bfloat16 a1 = __float2bfloat16_rn(v0);
    float r = v0 - __bfloat162float(a1);
    __nv_bfloat16 a2 = __float2bfloat16_rn(r);
    __nv_bfloat16 a3 = __float2bfloat16_rn(r - __bfloat162float(a2));
    __nv_bfloat16 b1 = __float2bfloat16_rn(v1);
    float r2 = v1 - __bfloat162float(b1);
    __nv_bfloat16 b2 = __float2bfloat16_rn(r2);
    __nv_bfloat16 b3 = __float2bfloat16_rn(r2 - __bfloat162float(b2));
    size_t o = (size_t)n * KP + k;
    *(__nv_bfloat162*)&g_Wt[0][o] = __nv_bfloat162(a1, b1);
    *(__nv_bfloat162*)&g_Wt[1][o] = __nv_bfloat162(a2, b2);
    *(__nv_bfloat162*)&g_Wt[2][o] = __nv_bfloat162(a3, b3);
}

// R^T splits: g_Rt[p][h][j] = split_p(R[j][h])
__global__ void split_r_kernel(const float* __restrict__ R) {
    int i = blockIdx.x * blockDim.x + threadIdx.x;
    if (i >= HH * (HH / 2)) return;
    int h = i / (HH / 2);
    int j = (i % (HH / 2)) * 2;
    float v0 = R[(size_t)j * HH + h];
    float v1 = R[(size_t)(j + 1) * HH + h];
    __nv_bfloat16 a1 = __float2bfloat16_rn(v0);
    float r = v0 - __bfloat162float(a1);
    __nv_bfloat16 a2 = __float2bfloat16_rn(r);
    __nv_bfloat16 a3 = __float2bfloat16_rn(r - __bfloat162float(a2));
    __nv_bfloat16 b1 = __float2bfloat16_rn(v1);
    float r2 = v1 - __bfloat162float(b1);
    __nv_bfloat16 b2 = __float2bfloat16_rn(r2);
    __nv_bfloat16 b3 = __float2bfloat16_rn(r2 - __bfloat162float(b2));
    size_t o = (size_t)h * HH + j;
    *(__nv_bfloat162*)&g_Rt[0][o] = __nv_bfloat162(a1, b1);
    *(__nv_bfloat162*)&g_Rt[1][o] = __nv_bfloat162(a2, b2);
    *(__nv_bfloat162*)&g_Rt[2][o] = __nv_bfloat162(a3, b3);
}

// ---------------------------------------------------------------------------
// Phase 1 via warp-level mma.sync with a 2-stage cp.async pipeline (R13 win).
// ---------------------------------------------------------------------------
__device__ __forceinline__ void gemm_issue_load(uint32_t smb, int c, int stage,
                                                int m0, int n0, int tid) {
#pragma unroll
    for (int it = 0; it < 12; it++) {
        int i = it * 256 + tid;
        int tile = i >> 9;
        int r = i & 511;
        int row = r >> 2, seg = r & 3;
        const void* src;
        if (tile < 3)
            src = &((const uint4*)g_Xs[tile])[(size_t)(m0 + row) * (KP / 8) + c * 4 + seg];
        else
            src = &((const uint4*)g_Wt[tile - 3])[(size_t)(n0 + row) * (KP / 8) + c * 4 + seg];
        uint32_t dst = smb + stage * STG_BYTES + tile * (128 * TSTRIDE) + row * TSTRIDE + seg * 16;
        CP_ASYNC_CG(dst, src);
    }
    CP_ASYNC_COMMIT();
}

__global__ void __launch_bounds__(256, 1)
gemm_tc_kernel() {
    extern __shared__ char dynsm[];
    const uint32_t smb = smem_u32(dynsm);

    const int tid = threadIdx.x;
    const int wid = tid >> 5;
    const int lane = tid & 31;
    const int n0 = (blockIdx.x & 7) * 128;
    const int m0 = (blockIdx.x >> 3) * 128;
    const int wm = (wid & 1) * 64;
    const int wn = (wid >> 1) * 32;

    float acc[4][4][4];
#pragma unroll
    for (int a = 0; a < 4; a++)
#pragma unroll
        for (int b = 0; b < 4; b++)
#pragma unroll
            for (int c = 0; c < 4; c++) acc[a][b][c] = 0.0f;

    const int pa[6] = {0, 0, 1, 1, 0, 2};
    const int pb[6] = {0, 1, 0, 1, 2, 0};

    const uint32_t a_off = (uint32_t)(lane & 15) * TSTRIDE + ((lane >> 4) << 4);
    const uint32_t b_off = (uint32_t)((lane & 7) + ((lane >> 4) << 3)) * TSTRIDE +
                           (((lane >> 3) & 1) << 4);

    gemm_issue_load(smb, 0, 0, m0, n0, tid);   // prologue

    for (int c = 0; c < NCH; c++) {
        const int s = c & 1;
        if (c + 1 < NCH) {
            gemm_issue_load(smb, c + 1, s ^ 1, m0, n0, tid);
            CP_ASYNC_WAIT(1);
        } else {
            CP_ASYNC_WAIT(0);
        }
        __syncthreads();

        const uint32_t sbase = smb + s * STG_BYTES;
#pragma unroll
        for (int q = 0; q < 6; q++) {
            uint32_t Ab = sbase + pa[q] * (128 * TSTRIDE);
            uint32_t Bb = sbase + (3 + pb[q]) * (128 * TSTRIDE);
#pragma unroll
            for (int ks = 0; ks < 2; ks++) {
                uint32_t b0[4], b1[4];
                asm volatile("ldmatrix.sync.aligned.m8n8.x4.shared.b16 {%0,%1,%2,%3}, [%4];"
                             : "=r"(b0[0]), "=r"(b0[1]), "=r"(b0[2]), "=r"(b0[3])
                             : "r"(Bb + (wn + 0) * TSTRIDE + b_off + ks * 32));
                asm volatile("ldmatrix.sync.aligned.m8n8.x4.shared.b16 {%0,%1,%2,%3}, [%4];"
                             : "=r"(b1[0]), "=r"(b1[1]), "=r"(b1[2]), "=r"(b1[3])
                             : "r"(Bb + (wn + 16) * TSTRIDE + b_off + ks * 32));
#pragma unroll
                for (int mf = 0; mf < 4; mf++) {
                    uint32_t a[4];
                    asm volatile("ldmatrix.sync.aligned.m8n8.x4.shared.b16 {%0,%1,%2,%3}, [%4];"
                                 : "=r"(a[0]), "=r"(a[1]), "=r"(a[2]), "=r"(a[3])
                                 : "r"(Ab + (wm + mf * 16) * TSTRIDE + a_off + ks * 32));
#pragma unroll
                    for (int nf = 0; nf < 4; nf++) {
                        uint32_t* bp = (nf < 2) ? &b0[(nf & 1) * 2] : &b1[(nf & 1) * 2];
                        asm volatile(
                            "mma.sync.aligned.m16n8k16.row.col.f32.bf16.bf16.f32 "
                            "{%0,%1,%2,%3}, {%4,%5,%6,%7}, {%8,%9}, {%0,%1,%2,%3};"
                            : "+f"(acc[mf][nf][0]), "+f"(acc[mf][nf][1]),
                              "+f"(acc[mf][nf][2]), "+f"(acc[mf][nf][3])
                            : "r"(a[0]), "r"(a[1]), "r"(a[2]), "r"(a[3]),
                              "r"(bp[0]), "r"(bp[1]));
                    }
                }
            }
        }
        __syncthreads();
    }

    const int mrow = m0 + wm + (lane >> 2);
    const int ncol = n0 + wn + (lane & 3) * 2;
#pragma unroll
    for (int mf = 0; mf < 4; mf++)
#pragma unroll
        for (int nf = 0; nf < 4; nf++) {
            size_t base = (size_t)(mrow + mf * 16) * HH + ncol + nf * 8;
            *(float2*)&g_C[base]          = make_float2(acc[mf][nf][0], acc[mf][nf][1]);
            *(float2*)&g_C[base + 8 * HH] = make_float2(acc[mf][nf][2], acc[mf][nf][3]);
        }
}

// ---------------------------------------------------------------------------
// Persistent recurrent kernel. R15 structure; barriers replaced with
// decentralized flag arrays (monotone counters, acquire/release).
// ---------------------------------------------------------------------------
__global__ void __launch_bounds__(NTHR, 1)
rsnn_persistent(float* __restrict__ out) {
    extern __shared__ char dynsm[];
    const uint32_t smA = smem_u32(dynsm);            // [128 b][ASTR]
    const uint32_t smR = smA + 128 * ASTR;           // 3 x [32 h][ASTR]

    const int bid = blockIdx.x;
    const int jt = bid >> 5;
    const int ht = bid & 31;
    const int j0 = jt * JTS;
    const int h0 = ht * HTS;
    const int tid = threadIdx.x;
    const int wid = tid >> 5;
    const int lane = tid & 31;
    const int wm = (wid & 3) * 32;
    const int wn = (wid >> 2) * 16;

    const uint32_t a_off = (uint32_t)(lane & 15) * ASTR + ((lane >> 4) << 4);
    const uint32_t b_off = (uint32_t)((lane & 7) + ((lane >> 4) << 3)) * ASTR +
                           (((lane >> 3) & 1) << 4);

    // Load resident R^T slice: 3 splits x [32 h][256 j]
    for (int i = tid; i < 3 * 32 * 32; i += NTHR) {
        int p = i >> 10;
        int r = (i >> 5) & 31;
        int seg = i & 31;
        uint4 v = __ldg(&((const uint4*)g_Rt[p])[((size_t)(h0 + r) * HH + j0) / 8 + seg]);
        uint32_t dst = smR + p * (32 * ASTR) + r * ASTR + seg * 16;
        asm volatile("st.shared.v4.b32 [%0], {%1,%2,%3,%4};"
                     :: "r"(dst), "r"(v.x), "r"(v.y), "r"(v.z), "r"(v.w) : "memory");
    }

    // LIF ownership: 4 consecutive h per thread
    const int e0 = (bid * NTHR + tid) * 4;
    const int bl = e0 >> 10;
    const int hl = e0 & 1023;
    float mem[4] = {0.f, 0.f, 0.f, 0.f};
    float spk[4] = {0.f, 0.f, 0.f, 0.f};

    for (int t = 0; t < TT; t++) {
        const __nv_bfloat16* __restrict__ sb = g_spkb[t & 1];

        // prefetch input current early (independent of this step's spikes)
        float4 cur = *(const float4*)&g_C[((size_t)bl * TT + t) * HH + hl];

        // stage spike tile in 2 cp.async chunks: j-bytes [0,256) and [256,512)
#pragma unroll
        for (int it = 0; it < 8; it++) {
            int i = it * NTHR + tid;          // 0..2047
            int row = i >> 4;
            int seg = i & 15;
            CP_ASYNC_CG(smA + row * ASTR + seg * 16,
                        &sb[(size_t)row * HH + j0 + seg * 8]);
        }
        CP_ASYNC_COMMIT();
#pragma unroll
        for (int it = 0; it < 8; it++) {
            int i = it * NTHR + tid;
            int row = i >> 4;
            int seg = 16 + (i & 15);
            CP_ASYNC_CG(smA + row * ASTR + seg * 16,
                        &sb[(size_t)row * HH + j0 + seg * 8]);
        }
        CP_ASYNC_COMMIT();

        float acc[2][2][4];
#pragma unroll
        for (int a = 0; a < 2; a++)
#pragma unroll
            for (int b = 0; b < 2; b++)
#pragma unroll
                for (int c = 0; c < 4; c++) acc[a][b][c] = 0.0f;

        CP_ASYNC_WAIT(1);          // chunk0 resident; chunk1 in flight
        __syncthreads();

#pragma unroll
        for (int half = 0; half < 2; half++) {
            if (half == 1) {
                CP_ASYNC_WAIT(0);  // chunk1 resident
                __syncthreads();
            }
#pragma unroll
            for (int k8 = 0; k8 < 8; k8++) {
                const int ks = half * 8 + k8;
                uint32_t a[2][4];
#pragma unroll
                for (int mf = 0; mf < 2; mf++)
                    asm volatile("ldmatrix.sync.aligned.m8n8.x4.shared.b16 {%0,%1,%2,%3}, [%4];"
                                 : "=r"(a[mf][0]), "=r"(a[mf][1]), "=r"(a[mf][2]), "=r"(a[mf][3])
                                 : "r"(smA + (wm + mf * 16) * ASTR + a_off + ks * 32));
#pragma unroll
                for (int p = 0; p < 3; p++) {
                    uint32_t bfr[4];
                    asm volatile("ldmatrix.sync.aligned.m8n8.x4.shared.b16 {%0,%1,%2,%3}, [%4];"
                                 : "=r"(bfr[0]), "=r"(bfr[1]), "=r"(bfr[2]), "=r"(bfr[3])
                                 : "r"(smR + p * (32 * ASTR) + wn * ASTR + b_off + ks * 32));
#pragma unroll
                    for (int mf = 0; mf < 2; mf++)
#pragma unroll
                        for (int nf = 0; nf < 2; nf++) {
                            asm volatile(
                                "mma.sync.aligned.m16n8k16.row.col.f32.bf16.bf16.f32 "
                                "{%0,%1,%2,%3}, {%4,%5,%6,%7}, {%8,%9}, {%0,%1,%2,%3};"
                                : "+f"(acc[mf][nf][0]), "+f"(acc[mf][nf][1]),
                                  "+f"(acc[mf][nf][2]), "+f"(acc[mf][nf][3])
                                : "r"(a[mf][0]), "r"(a[mf][1]), "r"(a[mf][2]), "r"(a[mf][3]),
                                  "r"(bfr[nf * 2]), "r"(bfr[nf * 2 + 1]));
                        }
                }
            }
        }

        // write partials: warp tile m32 x n16 at (wm, h0+wn)
        {
            const int mrow = wm + (lane >> 2);
            const int ncol = h0 + wn + (lane & 3) * 2;
#pragma unroll
            for (int mf = 0; mf < 2; mf++)
#pragma unroll
                for (int nf = 0; nf < 2; nf++) {
                    *(float2*)&g_part[jt][mrow + mf * 16][ncol + nf * 8] =
                        make_float2(acc[mf][nf][0], acc[mf][nf][1]);
                    *(float2*)&g_part[jt][mrow + mf * 16 + 8][ncol + nf * 8] =
                        make_float2(acc[mf][nf][2], acc[mf][nf][3]);
                }
        }
        grid_sync_arr(g_barA, (unsigned)(t + 1));

        // LIF phase: 4 owned elements (b = bl, h = hl..hl+3)
        {
            float c4[4] = {cur.x, cur.y, cur.z, cur.w};
#pragma unroll
            for (int q = 0; q < NJT; q++) {
                float4 pv = __ldcg((const float4*)&g_part[q][bl][hl]);
                c4[0] += pv.x; c4[1] += pv.y; c4[2] += pv.z; c4[3] += pv.w;
            }
            __nv_bfloat16* so = g_spkb[(t + 1) & 1];
#pragma unroll
            for (int i = 0; i < 4; i++) {
                mem[i] = __fadd_rn(__fmul_rn(__fmul_rn(mem[i], DECAY), 1.0f - spk[i]), c4[i]);
                spk[i] = (mem[i] >= 1.0f) ? 1.0f : 0.0f;
            }
            *(__nv_bfloat162*)&so[bl * HH + hl] =
                __nv_bfloat162(__float2bfloat16_rn(spk[0]), __float2bfloat16_rn(spk[1]));
            *(__nv_bfloat162*)&so[bl * HH + hl + 2] =
                __nv_bfloat162(__float2bfloat16_rn(spk[2]), __float2bfloat16_rn(spk[3]));
            if (hl < NS) {
                float* op = &out[((size_t)bl * TT + t) * NS + hl];
#pragma unroll
                for (int i = 0; i < 4; i++)
                    if (hl + i < NS) op[i] = spk[i];
            }
        }
        if (t + 1 < TT)
            grid_sync_arr(g_barB, (unsigned)(t + 1));
    }
}

// ---------------------------------------------------------------------------
extern "C" void kernel_launch(void* const* d_in, const int* in_sizes, int n_in,
                              void* d_out, int out_size) {
    const float* x   = (const float*)d_in[0];
    const float* fc1 = (const float*)d_in[1];
    const float* rec = (const float*)d_in[2];
    float* out = (float*)d_out;

    const int smem_g = 2 * STG_BYTES;                // 122,880 B (2-stage)
    cudaFuncSetAttribute(gemm_tc_kernel,
                         cudaFuncAttributeMaxDynamicSharedMemorySize, smem_g);
    const int smem_p = 128 * ASTR + 3 * 32 * ASTR;   // 118,272 B
    cudaFuncSetAttribute(rsnn_persistent,
                         cudaFuncAttributeMaxDynamicSharedMemorySize, smem_p);

    init_kernel<<<(BB * HH + 255) / 256, 256>>>(out, out_size);
    split_x_kernel<<<(BB * TT * (KP / 2) + 255) / 256, 256>>>(x);
    split_w_kernel<<<(HH * (KP / 2) + 255) / 256, 256>>>(fc1);
    split_r_kernel<<<(HH * (HH / 2) + 255) / 256, 256>>>(rec);
    gemm_tc_kernel<<<4000, 256, smem_g>>>();
    rsnn_persistent<<<NBLK, NTHR, smem_p>>>(out);
}

// round 17
// speedup vs baseline: 2.0644x; 2.0644x over previous
#include <cuda_runtime.h>
#include <cuda_bf16.h>
#include <cstdint>

// Problem constants
#define BB   128
#define TT   500
#define NIN  784
#define HH   1024
#define NS   102
#define DECAY 0.8807970779778823f      // sigmoid(2.0)
#define KP   832                       // NIN padded (multiple of 32)
#define KC   32
#define NCH  (KP / KC)
#define TSTRIDE 80                     // phase-1 smem row stride
#define STG_BYTES (6 * 128 * TSTRIDE)  // one pipeline stage: 61,440 B

// Persistent recurrent decomposition
#define NBLK 128
#define NTHR 256
#define NJT  4
#define JTS  256                       // j per tile
#define HTS  32                        // h per tile
#define ASTR 528                       // smem row stride bytes (512 data + 16 pad)

// Scratch
__device__ float g_C[(size_t)BB * TT * HH];              // X @ fc1  (262 MB)
__device__ float g_part[NJT][BB][HH];                    // j-partials (2 MB)
__device__ __nv_bfloat16 g_spkb[2][BB * HH];             // spike state, bf16, dbl-buf
__device__ unsigned g_bar_cnt;
__device__ volatile unsigned g_bar_gen;
__device__ __nv_bfloat16 g_Xs[3][(size_t)BB * TT * KP];  // X splits (320 MB)
__device__ __nv_bfloat16 g_Wt[3][(size_t)HH * KP];       // fc1^T splits (5 MB)
__device__ __nv_bfloat16 g_Rt[3][(size_t)HH * HH];       // R^T splits (6 MB)

__device__ __forceinline__ uint32_t smem_u32(const void* p) {
    uint32_t a;
    asm("{ .reg .u64 t; cvta.to.shared.u64 t, %1; cvt.u32.u64 %0, t; }" : "=r"(a) : "l"(p));
    return a;
}

#define CP_ASYNC_CG(dst, src) \
    asm volatile("cp.async.cg.shared.global [%0], [%1], 16;" :: "r"(dst), "l"(src) : "memory")
#define CP_ASYNC_COMMIT() asm volatile("cp.async.commit_group;" ::: "memory")
#define CP_ASYNC_WAIT(n)  asm volatile("cp.async.wait_group %0;" :: "n"(n) : "memory")

// ---------------------------------------------------------------------------
__global__ void init_kernel(float* __restrict__ out, int out_size) {
    int i = blockIdx.x * blockDim.x + threadIdx.x;
    if (i < BB * HH) {
        g_spkb[0][i] = __float2bfloat16_rn(0.f);
        g_spkb[1][i] = __float2bfloat16_rn(0.f);
    }
    if (i == 0) { g_bar_cnt = 0u; g_bar_gen = 0u; }
    int tail = out_size - BB * TT * NS;
    if (tail > 0 && i < tail) out[BB * TT * NS + i] = 500.0f;
}

// ---------------------------------------------------------------------------
// Exact 3-term bf16 splits.
// ---------------------------------------------------------------------------
__global__ void split_x_kernel(const float* __restrict__ X) {
    int i = blockIdx.x * blockDim.x + threadIdx.x;
    if (i >= BB * TT * (KP / 2)) return;
    int m = i / (KP / 2);
    int k = (i % (KP / 2)) * 2;
    float v0 = 0.f, v1 = 0.f;
    if (k < NIN) { v0 = X[(size_t)m * NIN + k]; v1 = X[(size_t)m * NIN + k + 1]; }
    __nv_bfloat16 a1 = __float2bfloat16_rn(v0);
    float r = v0 - __bfloat162float(a1);
    __nv_bfloat16 a2 = __float2bfloat16_rn(r);
    __nv_bfloat16 a3 = __float2bfloat16_rn(r - __bfloat162float(a2));
    __nv_bfloat16 b1 = __float2bfloat16_rn(v1);
    float r2 = v1 - __bfloat162float(b1);
    __nv_bfloat16 b2 = __float2bfloat16_rn(r2);
    __nv_bfloat16 b3 = __float2bfloat16_rn(r2 - __bfloat162float(b2));
    size_t o = (size_t)m * KP + k;
    *(__nv_bfloat162*)&g_Xs[0][o] = __nv_bfloat162(a1, b1);
    *(__nv_bfloat162*)&g_Xs[1][o] = __nv_bfloat162(a2, b2);
    *(__nv_bfloat162*)&g_Xs[2][o] = __nv_bfloat162(a3, b3);
}

__global__ void split_w_kernel(const float* __restrict__ W) {
    int i = blockIdx.x * blockDim.x + threadIdx.x;
    if (i >= HH * (KP / 2)) return;
    int n = i / (KP / 2);
    int k = (i % (KP / 2)) * 2;
    float v0 = (k < NIN)     ? W[(size_t)k * HH + n]       : 0.f;
    float v1 = (k + 1 < NIN) ? W[(size_t)(k + 1) * HH + n] : 0.f;
    __nv_bfloat16 a1 = __float2bfloat16_rn(v0);
    float r = v0 - __bfloat162float(a1);
    __nv_bfloat16 a2 = __float2bfloat16_rn(r);
    __nv_bfloat16 a3 = __float2bfloat16_rn(r - __bfloat162float(a2));
    __nv_bfloat16 b1 = __float2bfloat16_rn(v1);
    float r2 = v1 - __bfloat162float(b1);
    __nv_bfloat16 b2 = __float2bfloat16_rn(r2);
    __nv_bfloat16 b3 = __float2bfloat16_rn(r2 - __bfloat162float(b2));
    size_t o = (size_t)n * KP + k;
    *(__nv_bfloat162*)&g_Wt[0][o] = __nv_bfloat162(a1, b1);
    *(__nv_bfloat162*)&g_Wt[1][o] = __nv_bfloat162(a2, b2);
    *(__nv_bfloat162*)&g_Wt[2][o] = __nv_bfloat162(a3, b3);
}

// R^T splits: g_Rt[p][h][j] = split_p(R[j][h])
__global__ void split_r_kernel(const float* __restrict__ R) {
    int i = blockIdx.x * blockDim.x + threadIdx.x;
    if (i >= HH * (HH / 2)) return;
    int h = i / (HH / 2);
    int j = (i % (HH / 2)) * 2;
    float v0 = R[(size_t)j * HH + h];
    float v1 = R[(size_t)(j + 1) * HH + h];
    __nv_bfloat16 a1 = __float2bfloat16_rn(v0);
    float r = v0 - __bfloat162float(a1);
    __nv_bfloat16 a2 = __float2bfloat16_rn(r);
    __nv_bfloat16 a3 = __float2bfloat16_rn(r - __bfloat162float(a2));
    __nv_bfloat16 b1 = __float2bfloat16_rn(v1);
    float r2 = v1 - __bfloat162float(b1);
    __nv_bfloat16 b2 = __float2bfloat16_rn(r2);
    __nv_bfloat16 b3 = __float2bfloat16_rn(r2 - __bfloat162float(b2));
    size_t o = (size_t)h * HH + j;
    *(__nv_bfloat162*)&g_Rt[0][o] = __nv_bfloat162(a1, b1);
    *(__nv_bfloat162*)&g_Rt[1][o] = __nv_bfloat162(a2, b2);
    *(__nv_bfloat162*)&g_Rt[2][o] = __nv_bfloat162(a3, b3);
}

// ---------------------------------------------------------------------------
// Phase 1 via warp-level mma.sync with a 2-stage cp.async pipeline (R13 win).
// ---------------------------------------------------------------------------
__device__ __forceinline__ void gemm_issue_load(uint32_t smb, int c, int stage,
                                                int m0, int n0, int tid) {
#pragma unroll
    for (int it = 0; it < 12; it++) {
        int i = it * 256 + tid;
        int tile = i >> 9;
        int r = i & 511;
        int row = r >> 2, seg = r & 3;
        const void* src;
        if (tile < 3)
            src = &((const uint4*)g_Xs[tile])[(size_t)(m0 + row) * (KP / 8) + c * 4 + seg];
        else
            src = &((const uint4*)g_Wt[tile - 3])[(size_t)(n0 + row) * (KP / 8) + c * 4 + seg];
        uint32_t dst = smb + stage * STG_BYTES + tile * (128 * TSTRIDE) + row * TSTRIDE + seg * 16;
        CP_ASYNC_CG(dst, src);
    }
    CP_ASYNC_COMMIT();
}

__global__ void __launch_bounds__(256, 1)
gemm_tc_kernel() {
    extern __shared__ char dynsm[];
    const uint32_t smb = smem_u32(dynsm);

    const int tid = threadIdx.x;
    const int wid = tid >> 5;
    const int lane = tid & 31;
    const int n0 = (blockIdx.x & 7) * 128;
    const int m0 = (blockIdx.x >> 3) * 128;
    const int wm = (wid & 1) * 64;
    const int wn = (wid >> 1) * 32;

    float acc[4][4][4];
#pragma unroll
    for (int a = 0; a < 4; a++)
#pragma unroll
        for (int b = 0; b < 4; b++)
#pragma unroll
            for (int c = 0; c < 4; c++) acc[a][b][c] = 0.0f;

    const int pa[6] = {0, 0, 1, 1, 0, 2};
    const int pb[6] = {0, 1, 0, 1, 2, 0};

    const uint32_t a_off = (uint32_t)(lane & 15) * TSTRIDE + ((lane >> 4) << 4);
    const uint32_t b_off = (uint32_t)((lane & 7) + ((lane >> 4) << 3)) * TSTRIDE +
                           (((lane >> 3) & 1) << 4);

    gemm_issue_load(smb, 0, 0, m0, n0, tid);   // prologue

    for (int c = 0; c < NCH; c++) {
        const int s = c & 1;
        if (c + 1 < NCH) {
            gemm_issue_load(smb, c + 1, s ^ 1, m0, n0, tid);
            CP_ASYNC_WAIT(1);
        } else {
            CP_ASYNC_WAIT(0);
        }
        __syncthreads();

        const uint32_t sbase = smb + s * STG_BYTES;
#pragma unroll
        for (int q = 0; q < 6; q++) {
            uint32_t Ab = sbase + pa[q] * (128 * TSTRIDE);
            uint32_t Bb = sbase + (3 + pb[q]) * (128 * TSTRIDE);
#pragma unroll
            for (int ks = 0; ks < 2; ks++) {
                uint32_t b0[4], b1[4];
                asm volatile("ldmatrix.sync.aligned.m8n8.x4.shared.b16 {%0,%1,%2,%3}, [%4];"
                             : "=r"(b0[0]), "=r"(b0[1]), "=r"(b0[2]), "=r"(b0[3])
                             : "r"(Bb + (wn + 0) * TSTRIDE + b_off + ks * 32));
                asm volatile("ldmatrix.sync.aligned.m8n8.x4.shared.b16 {%0,%1,%2,%3}, [%4];"
                             : "=r"(b1[0]), "=r"(b1[1]), "=r"(b1[2]), "=r"(b1[3])
                             : "r"(Bb + (wn + 16) * TSTRIDE + b_off + ks * 32));
#pragma unroll
                for (int mf = 0; mf < 4; mf++) {
                    uint32_t a[4];
                    asm volatile("ldmatrix.sync.aligned.m8n8.x4.shared.b16 {%0,%1,%2,%3}, [%4];"
                                 : "=r"(a[0]), "=r"(a[1]), "=r"(a[2]), "=r"(a[3])
                                 : "r"(Ab + (wm + mf * 16) * TSTRIDE + a_off + ks * 32));
#pragma unroll
                    for (int nf = 0; nf < 4; nf++) {
                        uint32_t* bp = (nf < 2) ? &b0[(nf & 1) * 2] : &b1[(nf & 1) * 2];
                        asm volatile(
                            "mma.sync.aligned.m16n8k16.row.col.f32.bf16.bf16.f32 "
                            "{%0,%1,%2,%3}, {%4,%5,%6,%7}, {%8,%9}, {%0,%1,%2,%3};"
                            : "+f"(acc[mf][nf][0]), "+f"(acc[mf][nf][1]),
                              "+f"(acc[mf][nf][2]), "+f"(acc[mf][nf][3])
                            : "r"(a[0]), "r"(a[1]), "r"(a[2]), "r"(a[3]),
                              "r"(bp[0]), "r"(bp[1]));
                    }
                }
            }
        }
        __syncthreads();
    }

    const int mrow = m0 + wm + (lane >> 2);
    const int ncol = n0 + wn + (lane & 3) * 2;
#pragma unroll
    for (int mf = 0; mf < 4; mf++)
#pragma unroll
        for (int nf = 0; nf < 4; nf++) {
            size_t base = (size_t)(mrow + mf * 16) * HH + ncol + nf * 8;
            *(float2*)&g_C[base]          = make_float2(acc[mf][nf][0], acc[mf][nf][1]);
            *(float2*)&g_C[base + 8 * HH] = make_float2(acc[mf][nf][2], acc[mf][nf][3]);
        }
}

// ---------------------------------------------------------------------------
// Centralized grid barrier (R11/R15 proven — do not modify).
// ---------------------------------------------------------------------------
__device__ __forceinline__ void grid_sync() {
    __threadfence();
    __syncthreads();
    if (threadIdx.x == 0) {
        unsigned gen = g_bar_gen;
        if (atomicAdd(&g_bar_cnt, 1u) == NBLK - 1) {
            g_bar_cnt = 0;
            __threadfence();
            g_bar_gen = gen + 1;
        } else {
            while (g_bar_gen == gen) __nanosleep(40);
        }
        __threadfence();
    }
    __syncthreads();
}

// ---------------------------------------------------------------------------
// Persistent recurrent kernel (R15 winner) + p=0 R-fragments hoisted into
// registers (loop-invariant; 64 regs, safe at 1 CTA/SM). Bit-identical math.
// ---------------------------------------------------------------------------
__global__ void __launch_bounds__(NTHR, 1)
rsnn_persistent(float* __restrict__ out) {
    extern __shared__ char dynsm[];
    const uint32_t smA = smem_u32(dynsm);            // [128 b][ASTR]
    const uint32_t smR = smA + 128 * ASTR;           // 3 x [32 h][ASTR]

    const int bid = blockIdx.x;
    const int jt = bid >> 5;
    const int ht = bid & 31;
    const int j0 = jt * JTS;
    const int h0 = ht * HTS;
    const int tid = threadIdx.x;
    const int wid = tid >> 5;
    const int lane = tid & 31;
    const int wm = (wid & 3) * 32;
    const int wn = (wid >> 2) * 16;

    const uint32_t a_off = (uint32_t)(lane & 15) * ASTR + ((lane >> 4) << 4);
    const uint32_t b_off = (uint32_t)((lane & 7) + ((lane >> 4) << 3)) * ASTR +
                           (((lane >> 3) & 1) << 4);

    // Load resident R^T slice: 3 splits x [32 h][256 j]
    for (int i = tid; i < 3 * 32 * 32; i += NTHR) {
        int p = i >> 10;
        int r = (i >> 5) & 31;
        int seg = i & 31;
        uint4 v = __ldg(&((const uint4*)g_Rt[p])[((size_t)(h0 + r) * HH + j0) / 8 + seg]);
        uint32_t dst = smR + p * (32 * ASTR) + r * ASTR + seg * 16;
        asm volatile("st.shared.v4.b32 [%0], {%1,%2,%3,%4};"
                     :: "r"(dst), "r"(v.x), "r"(v.y), "r"(v.z), "r"(v.w) : "memory");
    }
    __syncthreads();

    // Hoist p=0 R fragments into registers (constant across all 500 steps)
    uint32_t r0f[16][4];
#pragma unroll
    for (int ks = 0; ks < 16; ks++)
        asm volatile("ldmatrix.sync.aligned.m8n8.x4.shared.b16 {%0,%1,%2,%3}, [%4];"
                     : "=r"(r0f[ks][0]), "=r"(r0f[ks][1]), "=r"(r0f[ks][2]), "=r"(r0f[ks][3])
                     : "r"(smR + wn * ASTR + b_off + ks * 32));

    // LIF ownership: 4 consecutive h per thread
    const int e0 = (bid * NTHR + tid) * 4;
    const int bl = e0 >> 10;
    const int hl = e0 & 1023;
    float mem[4] = {0.f, 0.f, 0.f, 0.f};
    float spk[4] = {0.f, 0.f, 0.f, 0.f};

    for (int t = 0; t < TT; t++) {
        const __nv_bfloat16* __restrict__ sb = g_spkb[t & 1];

        // prefetch input current early (independent of this step's spikes)
        float4 cur = *(const float4*)&g_C[((size_t)bl * TT + t) * HH + hl];

        // stage spike tile in 2 cp.async chunks: j-bytes [0,256) and [256,512)
#pragma unroll
        for (int it = 0; it < 8; it++) {
            int i = it * NTHR + tid;          // 0..2047
            int row = i >> 4;
            int seg = i & 15;
            CP_ASYNC_CG(smA + row * ASTR + seg * 16,
                        &sb[(size_t)row * HH + j0 + seg * 8]);
        }
        CP_ASYNC_COMMIT();
#pragma unroll
        for (int it = 0; it < 8; it++) {
            int i = it * NTHR + tid;
            int row = i >> 4;
            int seg = 16 + (i & 15);
            CP_ASYNC_CG(smA + row * ASTR + seg * 16,
                        &sb[(size_t)row * HH + j0 + seg * 8]);
        }
        CP_ASYNC_COMMIT();

        float acc[2][2][4];
#pragma unroll
        for (int a = 0; a < 2; a++)
#pragma unroll
            for (int b = 0; b < 2; b++)
#pragma unroll
                for (int c = 0; c < 4; c++) acc[a][b][c] = 0.0f;

        CP_ASYNC_WAIT(1);          // chunk0 resident; chunk1 in flight
        __syncthreads();

#pragma unroll
        for (int half = 0; half < 2; half++) {
            if (half == 1) {
                CP_ASYNC_WAIT(0);  // chunk1 resident
                __syncthreads();
            }
#pragma unroll
            for (int k8 = 0; k8 < 8; k8++) {
                const int ks = half * 8 + k8;
                uint32_t a[2][4];
#pragma unroll
                for (int mf = 0; mf < 2; mf++)
                    asm volatile("ldmatrix.sync.aligned.m8n8.x4.shared.b16 {%0,%1,%2,%3}, [%4];"
                                 : "=r"(a[mf][0]), "=r"(a[mf][1]), "=r"(a[mf][2]), "=r"(a[mf][3])
                                 : "r"(smA + (wm + mf * 16) * ASTR + a_off + ks * 32));
#pragma unroll
                for (int p = 0; p < 3; p++) {
                    uint32_t bfr[4];
                    if (p == 0) {
                        bfr[0] = r0f[ks][0]; bfr[1] = r0f[ks][1];
                        bfr[2] = r0f[ks][2]; bfr[3] = r0f[ks][3];
                    } else {
                        asm volatile("ldmatrix.sync.aligned.m8n8.x4.shared.b16 {%0,%1,%2,%3}, [%4];"
                                     : "=r"(bfr[0]), "=r"(bfr[1]), "=r"(bfr[2]), "=r"(bfr[3])
                                     : "r"(smR + p * (32 * ASTR) + wn * ASTR + b_off + ks * 32));
                    }
#pragma unroll
                    for (int mf = 0; mf < 2; mf++)
#pragma unroll
                        for (int nf = 0; nf < 2; nf++) {
                            asm volatile(
                                "mma.sync.aligned.m16n8k16.row.col.f32.bf16.bf16.f32 "
                                "{%0,%1,%2,%3}, {%4,%5,%6,%7}, {%8,%9}, {%0,%1,%2,%3};"
                                : "+f"(acc[mf][nf][0]), "+f"(acc[mf][nf][1]),
                                  "+f"(acc[mf][nf][2]), "+f"(acc[mf][nf][3])
                                : "r"(a[mf][0]), "r"(a[mf][1]), "r"(a[mf][2]), "r"(a[mf][3]),
                                  "r"(bfr[nf * 2]), "r"(bfr[nf * 2 + 1]));
                        }
                }
            }
        }

        // write partials: warp tile m32 x n16 at (wm, h0+wn)
        {
            const int mrow = wm + (lane >> 2);
            const int ncol = h0 + wn + (lane & 3) * 2;
#pragma unroll
            for (int mf = 0; mf < 2; mf++)
#pragma unroll
                for (int nf = 0; nf < 2; nf++) {
                    *(float2*)&g_part[jt][mrow + mf * 16][ncol + nf * 8] =
                        make_float2(acc[mf][nf][0], acc[mf][nf][1]);
                    *(float2*)&g_part[jt][mrow + mf * 16 + 8][ncol + nf * 8] =
                        make_float2(acc[mf][nf][2], acc[mf][nf][3]);
                }
        }
        grid_sync();

        // LIF phase: 4 owned elements (b = bl, h = hl..hl+3)
        {
            float c4[4] = {cur.x, cur.y, cur.z, cur.w};
#pragma unroll
            for (int q = 0; q < NJT; q++) {
                float4 pv = __ldcg((const float4*)&g_part[q][bl][hl]);
                c4[0] += pv.x; c4[1] += pv.y; c4[2] += pv.z; c4[3] += pv.w;
            }
            __nv_bfloat16* so = g_spkb[(t + 1) & 1];
#pragma unroll
            for (int i = 0; i < 4; i++) {
                mem[i] = __fadd_rn(__fmul_rn(__fmul_rn(mem[i], DECAY), 1.0f - spk[i]), c4[i]);
                spk[i] = (mem[i] >= 1.0f) ? 1.0f : 0.0f;
            }
            *(__nv_bfloat162*)&so[bl * HH + hl] =
                __nv_bfloat162(__float2bfloat16_rn(spk[0]), __float2bfloat16_rn(spk[1]));
            *(__nv_bfloat162*)&so[bl * HH + hl + 2] =
                __nv_bfloat162(__float2bfloat16_rn(spk[2]), __float2bfloat16_rn(spk[3]));
            if (hl < NS) {
                float* op = &out[((size_t)bl * TT + t) * NS + hl];
#pragma unroll
                for (int i = 0; i < 4; i++)
                    if (hl + i < NS) op[i] = spk[i];
            }
        }
        grid_sync();
    }
}

// ---------------------------------------------------------------------------
extern "C" void kernel_launch(void* const* d_in, const int* in_sizes, int n_in,
                              void* d_out, int out_size) {
    const float* x   = (const float*)d_in[0];
    const float* fc1 = (const float*)d_in[1];
    const float* rec = (const float*)d_in[2];
    float* out = (float*)d_out;

    const int smem_g = 2 * STG_BYTES;                // 122,880 B (2-stage)
    cudaFuncSetAttribute(gemm_tc_kernel,
                         cudaFuncAttributeMaxDynamicSharedMemorySize, smem_g);
    const int smem_p = 128 * ASTR + 3 * 32 * ASTR;   // 118,272 B
    cudaFuncSetAttribute(rsnn_persistent,
                         cudaFuncAttributeMaxDynamicSharedMemorySize, smem_p);

    init_kernel<<<(BB * HH + 255) / 256, 256>>>(out, out_size);
    split_x_kernel<<<(BB * TT * (KP / 2) + 255) / 256, 256>>>(x);
    split_w_kernel<<<(HH * (KP / 2) + 255) / 256, 256>>>(fc1);
    split_r_kernel<<<(HH * (HH / 2) + 255) / 256, 256>>>(rec);
    gemm_tc_kernel<<<4000, 256, smem_g>>>();
    rsnn_persistent<<<NBLK, NTHR, smem_p>>>(out);
}